// round 13
// baseline (speedup 1.0000x reference)
#include <cuda_runtime.h>

#define BINS  10
#define BLOCK 256
#define OCC   6
#define GRID  (148 * OCC)

// Global scratch (zero at module load; reset by last block each run -> graph-replayable).
__device__ float    g_sum[BINS];
__device__ float    g_cnt[BINS];
__device__ unsigned g_ticket;

#define LOG2E 1.4426950408889634f
#define LN2   0.69314718055994531f

__device__ __forceinline__ float rcp_approx(float p) {
    float r;
    asm("rcp.approx.f32 %0, %1;" : "=f"(r) : "f"(p));   // single MUFU.RCP
    return r;
}
__device__ __forceinline__ unsigned long long pack2(float lo, float hi) {
    unsigned long long v;
    asm("mov.b64 %0, {%1, %2};" : "=l"(v) : "f"(lo), "f"(hi));
    return v;
}

// rowbase = (char*)rows + tid*8 ; cell for bin b at rowbase + b*2048 (conflict-free:
// bank-pair = tid mod 16, bin term moves whole 32-bank rows).
__device__ __forceinline__ void ghm_elem(float xx, int tt, char* __restrict__ rowbase) {
    // z = x if t==0 else -x. Adding t<<31 flips only the sign bit -> 1 LEA.
    const int   zi = __float_as_int(xx) + (int)(((unsigned)tt) << 31);
    const float z  = __int_as_float(zi);
    const float a  = exp2f(z * LOG2E);            // e^z        (FMUL + MUFU.EX2)
    const float p  = 1.0f + a;                    // 1 + e^z    (inf-safe)
    const float l  = __log2f(p);                  // MUFU.LG2: ce = ln2 * l (scaled at finalize)
    const float r  = rcp_approx(p);               // MUFU.RCP (approx): sigmoid(z) = 1 - r
    const float g9 = 9.9999f - 9.9999f * r;       // FFMA: g*(BINS-1e-4) in [0, 9.9999)
    const int  bin = (int)g9;                     // F2I trunc; p=inf -> r=0 -> bin 9
    unsigned long long* cell = (unsigned long long*)(rowbase + (bin << 11));
    const unsigned long long inc = pack2(l, 1.0f);
    unsigned long long v = *cell;                               // LDS.64
    asm("add.rn.f32x2 %0, %0, %1;" : "+l"(v) : "l"(inc));       // packed (sum, cnt) add
    *cell = v;                                                  // STS.64
}

__global__ void __launch_bounds__(BLOCK, OCC)
ghm_fused(const float* __restrict__ x, const int* __restrict__ tg, int n,
          float* __restrict__ out, int out_size) {
    __shared__ float2 rows[BINS][BLOCK];   // [bin][tid]
    __shared__ float  sh_fin[2 * BINS];
    __shared__ bool   s_last;

    const int tid = threadIdx.x;
    char* __restrict__ rowbase = (char*)rows + tid * (int)sizeof(float2);
    #pragma unroll
    for (int b = 0; b < BINS; ++b) rows[b][tid] = make_float2(0.0f, 0.0f);

    const int n4      = n >> 2;
    const int stride4 = GRID * BLOCK;
    const int idx     = blockIdx.x * BLOCK + tid;
    const int per_it  = 2 * stride4;          // float4-groups per super-iteration (8 elems/thread)
    const int full    = n4 / per_it;          // fully-valid super-iterations (uniform)
    const float4* __restrict__ x4 = (const float4*)x;
    const int4*   __restrict__ t4 = (const int4*)tg;

    // Hot loop: 8 elems/thread/iter, 4 front-batched streaming LDG.128.
    for (int it = 0; it < full; ++it) {
        const int base = idx + it * per_it;
        float4 xv[2]; int4 tv[2];
        #pragma unroll
        for (int k = 0; k < 2; ++k) {
            xv[k] = __ldcs(&x4[base + k * stride4]);   // read-once: evict-first
            tv[k] = __ldcs(&t4[base + k * stride4]);
        }
        #pragma unroll
        for (int k = 0; k < 2; ++k) {
            ghm_elem(xv[k].x, tv[k].x, rowbase);
            ghm_elem(xv[k].y, tv[k].y, rowbase);
            ghm_elem(xv[k].z, tv[k].z, rowbase);
            ghm_elem(xv[k].w, tv[k].w, rowbase);
        }
    }

    // Ragged float4 tail.
    for (int i = idx + full * per_it; i < n4; i += stride4) {
        const float4 xv = __ldcs(&x4[i]);
        const int4   tv = __ldcs(&t4[i]);
        ghm_elem(xv.x, tv.x, rowbase);
        ghm_elem(xv.y, tv.y, rowbase);
        ghm_elem(xv.z, tv.z, rowbase);
        ghm_elem(xv.w, tv.w, rowbase);
    }

    // Scalar tail (n % 4), block 0 only.
    if (blockIdx.x == 0 && tid < (n & 3)) {
        const int i = (n & ~3) + tid;
        ghm_elem(x[i], tg[i], rowbase);
    }

    // ── Reduction: own smem column -> regs -> warp butterfly -> block -> global ──
    float sums[BINS], cnts[BINS];
    #pragma unroll
    for (int b = 0; b < BINS; ++b) {
        const float2 v = rows[b][tid];     // own cells only; no sync needed
        sums[b] = v.x; cnts[b] = v.y;
    }
    #pragma unroll
    for (int b = 0; b < BINS; ++b) {
        #pragma unroll
        for (int o = 16; o; o >>= 1) {
            sums[b] += __shfl_xor_sync(0xffffffffu, sums[b], o);
            cnts[b] += __shfl_xor_sync(0xffffffffu, cnts[b], o);
        }
    }
    if (tid < 2 * BINS) sh_fin[tid] = 0.0f;
    __syncthreads();
    if ((tid & 31) == 0) {
        #pragma unroll
        for (int b = 0; b < BINS; ++b) {
            atomicAdd(&sh_fin[b], sums[b]);
            atomicAdd(&sh_fin[BINS + b], cnts[b]);
        }
    }
    __syncthreads();
    if (tid < BINS) {
        atomicAdd(&g_sum[tid], sh_fin[tid]);
        atomicAdd(&g_cnt[tid], sh_fin[BINS + tid]);
    }

    // Last-block ticket: finalize + reset scratch for next graph replay.
    __threadfence();
    if (tid == 0) {
        const unsigned t = atomicAdd(&g_ticket, 1u);
        s_last = (t == (unsigned)(GRID - 1));
    }
    __syncthreads();
    if (s_last && tid < 32) {
        float c = 0.0f, ssum = 0.0f;
        if (tid < BINS) {
            c    = atomicAdd(&g_cnt[tid], 0.0f);   // coherent L2 read
            ssum = atomicAdd(&g_sum[tid], 0.0f);
        }
        const unsigned ne = __ballot_sync(0xffffffffu, (tid < BINS) && (c > 0.0f));
        const float nonempty = (float)__popc(ne);
        float term = 0.0f;
        if (tid < BINS)
            term = (LN2 * ssum) / fmaxf(c * nonempty, 1e-6f);  // deferred ln2 scale
        #pragma unroll
        for (int o = 16; o; o >>= 1)
            term += __shfl_xor_sync(0xffffffffu, term, o);
        for (int i = tid; i < out_size; i += 32) out[i] = term;
        if (tid < BINS) { g_sum[tid] = 0.0f; g_cnt[tid] = 0.0f; }
        if (tid == 0) g_ticket = 0u;
    }
}

extern "C" void kernel_launch(void* const* d_in, const int* in_sizes, int n_in,
                              void* d_out, int out_size) {
    const float* x = (const float*)d_in[0];
    const int*   t = (const int*)d_in[1];
    const int n = in_sizes[0];
    ghm_fused<<<GRID, BLOCK>>>(x, t, n, (float*)d_out, out_size);
}

// round 14
// speedup vs baseline: 1.1038x; 1.1038x over previous
#include <cuda_runtime.h>

#define BINS  10
#define BLOCK 256
#define OCC   4
#define GRID  (148 * OCC)

// Global scratch (zero at module load; reset by last block each run -> graph-replayable).
__device__ float    g_sum[BINS];
__device__ float    g_cnt[BINS];
__device__ unsigned g_ticket;

#define LOG2E 1.4426950408889634f
#define LN2   0.69314718055994531f

__device__ __forceinline__ float ex2_approx(float x) {
    float r; asm("ex2.approx.f32 %0, %1;" : "=f"(r) : "f"(x)); return r;   // MUFU.EX2
}
__device__ __forceinline__ float lg2_approx(float x) {
    float r; asm("lg2.approx.f32 %0, %1;" : "=f"(r) : "f"(x)); return r;   // MUFU.LG2
}
__device__ __forceinline__ float rcp_approx(float x) {
    float r; asm("rcp.approx.f32 %0, %1;" : "=f"(r) : "f"(x)); return r;   // MUFU.RCP
}
__device__ __forceinline__ unsigned long long pack2(float lo, float hi) {
    unsigned long long v;
    asm("mov.b64 %0, {%1, %2};" : "=l"(v) : "f"(lo), "f"(hi));
    return v;
}

// rowbase = (char*)rows + tid*8 ; cell for bin b at rowbase + b*2048 (conflict-free:
// bank-pair = tid mod 16, bin term moves whole 32-bank rows).
__device__ __forceinline__ void ghm_elem(float xx, int tt, char* __restrict__ rowbase) {
    // z = x if t==0 else -x. Adding t<<31 flips only the sign bit -> 1 LEA.
    const int   zi = __float_as_int(xx) + (int)(((unsigned)tt) << 31);
    const float z  = __int_as_float(zi);
    const float a  = ex2_approx(z * LOG2E);       // e^z      (FMUL + MUFU.EX2, no libm wrapper)
    const float p  = 1.0f + a;                    // 1 + e^z  (inf-safe)
    const float l  = lg2_approx(p);               // ce = ln2 * l (scaled at finalize)
    const float r  = rcp_approx(p);               // sigmoid(z) = 1 - r
    const float g9 = 9.9999f - 9.9999f * r;       // FFMA: g*(BINS-1e-4) in [0, 9.9999)
    const int  bin = (int)g9;                     // F2I trunc; p=inf -> r=0 -> bin 9
    unsigned long long* cell = (unsigned long long*)(rowbase + (bin << 11));
    const unsigned long long inc = pack2(l, 1.0f);
    unsigned long long v = *cell;                               // LDS.64
    asm("add.rn.f32x2 %0, %0, %1;" : "+l"(v) : "l"(inc));       // packed (sum, cnt) add
    *cell = v;                                                  // STS.64
}

__global__ void __launch_bounds__(BLOCK, OCC)
ghm_fused(const float* __restrict__ x, const int* __restrict__ tg, int n,
          float* __restrict__ out, int out_size) {
    __shared__ float2 rows[BINS][BLOCK];   // [bin][tid]
    __shared__ float  sh_fin[2 * BINS];
    __shared__ bool   s_last;

    const int tid = threadIdx.x;
    char* __restrict__ rowbase = (char*)rows + tid * (int)sizeof(float2);
    #pragma unroll
    for (int b = 0; b < BINS; ++b) rows[b][tid] = make_float2(0.0f, 0.0f);

    const int n4      = n >> 2;
    const int stride4 = GRID * BLOCK;
    const int idx     = blockIdx.x * BLOCK + tid;
    const int per_it  = 2 * stride4;          // 8 elems/thread per iteration
    const int full    = n4 / per_it;          // fully-valid iterations (uniform)
    const float4* __restrict__ x4 = (const float4*)x;
    const int4*   __restrict__ t4 = (const int4*)tg;

    // ── Software-pipelined hot loop: prefetch iter i+1 while consuming iter i ──
    float4 xA[2]; int4 tA[2];
    if (full > 0) {
        #pragma unroll
        for (int k = 0; k < 2; ++k) {
            xA[k] = __ldcs(&x4[idx + k * stride4]);
            tA[k] = __ldcs(&t4[idx + k * stride4]);
        }
    }
    #pragma unroll 2
    for (int it = 0; it + 1 < full; ++it) {
        const int nbase = idx + (it + 1) * per_it;
        float4 xB[2]; int4 tB[2];
        #pragma unroll
        for (int k = 0; k < 2; ++k) {                 // next iter's loads in flight...
            xB[k] = __ldcs(&x4[nbase + k * stride4]);
            tB[k] = __ldcs(&t4[nbase + k * stride4]);
        }
        #pragma unroll
        for (int k = 0; k < 2; ++k) {                 // ...while this iter computes
            ghm_elem(xA[k].x, tA[k].x, rowbase);
            ghm_elem(xA[k].y, tA[k].y, rowbase);
            ghm_elem(xA[k].z, tA[k].z, rowbase);
            ghm_elem(xA[k].w, tA[k].w, rowbase);
        }
        #pragma unroll
        for (int k = 0; k < 2; ++k) { xA[k] = xB[k]; tA[k] = tB[k]; }
    }
    if (full > 0) {
        #pragma unroll
        for (int k = 0; k < 2; ++k) {
            ghm_elem(xA[k].x, tA[k].x, rowbase);
            ghm_elem(xA[k].y, tA[k].y, rowbase);
            ghm_elem(xA[k].z, tA[k].z, rowbase);
            ghm_elem(xA[k].w, tA[k].w, rowbase);
        }
    }

    // Ragged float4 tail.
    for (int i = idx + full * per_it; i < n4; i += stride4) {
        const float4 xv = __ldcs(&x4[i]);
        const int4   tv = __ldcs(&t4[i]);
        ghm_elem(xv.x, tv.x, rowbase);
        ghm_elem(xv.y, tv.y, rowbase);
        ghm_elem(xv.z, tv.z, rowbase);
        ghm_elem(xv.w, tv.w, rowbase);
    }

    // Scalar tail (n % 4), block 0 only.
    if (blockIdx.x == 0 && tid < (n & 3)) {
        const int i = (n & ~3) + tid;
        ghm_elem(x[i], tg[i], rowbase);
    }

    // ── Reduction: own smem column -> regs -> warp butterfly -> block -> global ──
    float sums[BINS], cnts[BINS];
    #pragma unroll
    for (int b = 0; b < BINS; ++b) {
        const float2 v = rows[b][tid];     // own cells only; no sync needed
        sums[b] = v.x; cnts[b] = v.y;
    }
    #pragma unroll
    for (int b = 0; b < BINS; ++b) {
        #pragma unroll
        for (int o = 16; o; o >>= 1) {
            sums[b] += __shfl_xor_sync(0xffffffffu, sums[b], o);
            cnts[b] += __shfl_xor_sync(0xffffffffu, cnts[b], o);
        }
    }
    if (tid < 2 * BINS) sh_fin[tid] = 0.0f;
    __syncthreads();
    if ((tid & 31) == 0) {
        #pragma unroll
        for (int b = 0; b < BINS; ++b) {
            atomicAdd(&sh_fin[b], sums[b]);
            atomicAdd(&sh_fin[BINS + b], cnts[b]);
        }
    }
    __syncthreads();
    if (tid < BINS) {
        atomicAdd(&g_sum[tid], sh_fin[tid]);
        atomicAdd(&g_cnt[tid], sh_fin[BINS + tid]);
    }

    // Last-block ticket: finalize + reset scratch for next graph replay.
    __threadfence();
    if (tid == 0) {
        const unsigned t = atomicAdd(&g_ticket, 1u);
        s_last = (t == (unsigned)(GRID - 1));
    }
    __syncthreads();
    if (s_last && tid < 32) {
        float c = 0.0f, ssum = 0.0f;
        if (tid < BINS) {
            c    = atomicAdd(&g_cnt[tid], 0.0f);   // coherent L2 read
            ssum = atomicAdd(&g_sum[tid], 0.0f);
        }
        const unsigned ne = __ballot_sync(0xffffffffu, (tid < BINS) && (c > 0.0f));
        const float nonempty = (float)__popc(ne);
        float term = 0.0f;
        if (tid < BINS)
            term = (LN2 * ssum) / fmaxf(c * nonempty, 1e-6f);  // deferred ln2 scale
        #pragma unroll
        for (int o = 16; o; o >>= 1)
            term += __shfl_xor_sync(0xffffffffu, term, o);
        for (int i = tid; i < out_size; i += 32) out[i] = term;
        if (tid < BINS) { g_sum[tid] = 0.0f; g_cnt[tid] = 0.0f; }
        if (tid == 0) g_ticket = 0u;
    }
}

extern "C" void kernel_launch(void* const* d_in, const int* in_sizes, int n_in,
                              void* d_out, int out_size) {
    const float* x = (const float*)d_in[0];
    const int*   t = (const int*)d_in[1];
    const int n = in_sizes[0];
    ghm_fused<<<GRID, BLOCK>>>(x, t, n, (float*)d_out, out_size);
}

// round 15
// speedup vs baseline: 1.2007x; 1.0877x over previous
#include <cuda_runtime.h>

#define BINS  10
#define BLOCK 256
#define OCC   4
#define GRID  (148 * OCC)

// Global scratch (zero at module load; reset by last block each run -> graph-replayable).
__device__ float    g_sum[BINS];
__device__ float    g_cnt[BINS];
__device__ unsigned g_ticket;

#define LOG2E 1.4426950408889634f
#define LN2   0.69314718055994531f
#define KBIG  4096.0f            // count embedded as multiples of 4096 in the same float
#define KINV  (1.0f / 4096.0f)

__device__ __forceinline__ float ex2_approx(float x) {
    float r; asm("ex2.approx.f32 %0, %1;" : "=f"(r) : "f"(x)); return r;   // MUFU.EX2
}
__device__ __forceinline__ float lg2_approx(float x) {
    float r; asm("lg2.approx.f32 %0, %1;" : "=f"(r) : "f"(x)); return r;   // MUFU.LG2
}
__device__ __forceinline__ float rcp_approx(float x) {
    float r; asm("rcp.approx.f32 %0, %1;" : "=f"(r) : "f"(x)); return r;   // MUFU.RCP
}

// rowbase = (char*)rows + tid*4 ; cell for bin b at rowbase + b*1024 (conflict-free:
// bank = tid mod 32, bin term moves whole 32-bank rows).
__device__ __forceinline__ void ghm_elem(float xx, int tt, char* __restrict__ rowbase) {
    // z = x if t==0 else -x. Adding t<<31 flips only the sign bit -> 1 LEA.
    const int   zi = __float_as_int(xx) + (int)(((unsigned)tt) << 31);
    const float z  = __int_as_float(zi);
    const float a  = ex2_approx(z * LOG2E);       // e^z      (FMUL + MUFU.EX2)
    const float p  = 1.0f + a;                    // 1 + e^z  (inf-safe)
    const float l  = lg2_approx(p);               // ce = ln2 * l (scaled at finalize)
    const float r  = rcp_approx(p);               // sigmoid(z) = 1 - r
    const float g9 = 9.9999f - 9.9999f * r;       // FFMA: g*(BINS-1e-4) in [0, 9.9999)
    const int  bin = (int)g9;                     // F2I trunc; p=inf -> r=0 -> bin 9
    float* cell = (float*)(rowbase + (bin << 10));
    *cell += (l + KBIG);                          // LDS.32 + 2 FADD + STS.32
}

__global__ void __launch_bounds__(BLOCK, OCC)
ghm_fused(const float* __restrict__ x, const int* __restrict__ tg, int n,
          float* __restrict__ out, int out_size) {
    __shared__ float rows[BINS][BLOCK];    // [bin][tid]; S = 4096*cnt + sum(log2 p)
    __shared__ float sh_fin[2 * BINS];
    __shared__ bool  s_last;

    const int tid = threadIdx.x;
    char* __restrict__ rowbase = (char*)rows + tid * (int)sizeof(float);
    #pragma unroll
    for (int b = 0; b < BINS; ++b) rows[b][tid] = 0.0f;

    const int n4      = n >> 2;
    const int stride4 = GRID * BLOCK;
    const int idx     = blockIdx.x * BLOCK + tid;
    const int per_it  = 2 * stride4;          // 8 elems/thread per iteration
    const int full    = n4 / per_it;          // fully-valid iterations (uniform)
    const float4* __restrict__ x4 = (const float4*)x;
    const int4*   __restrict__ t4 = (const int4*)tg;

    // ── Software-pipelined hot loop: prefetch iter i+1 while consuming iter i ──
    float4 xA[2]; int4 tA[2];
    if (full > 0) {
        #pragma unroll
        for (int k = 0; k < 2; ++k) {
            xA[k] = __ldcs(&x4[idx + k * stride4]);
            tA[k] = __ldcs(&t4[idx + k * stride4]);
        }
    }
    #pragma unroll 2
    for (int it = 0; it + 1 < full; ++it) {
        const int nbase = idx + (it + 1) * per_it;
        float4 xB[2]; int4 tB[2];
        #pragma unroll
        for (int k = 0; k < 2; ++k) {                 // next iter's loads in flight...
            xB[k] = __ldcs(&x4[nbase + k * stride4]);
            tB[k] = __ldcs(&t4[nbase + k * stride4]);
        }
        #pragma unroll
        for (int k = 0; k < 2; ++k) {                 // ...while this iter computes
            ghm_elem(xA[k].x, tA[k].x, rowbase);
            ghm_elem(xA[k].y, tA[k].y, rowbase);
            ghm_elem(xA[k].z, tA[k].z, rowbase);
            ghm_elem(xA[k].w, tA[k].w, rowbase);
        }
        #pragma unroll
        for (int k = 0; k < 2; ++k) { xA[k] = xB[k]; tA[k] = tB[k]; }
    }
    if (full > 0) {
        #pragma unroll
        for (int k = 0; k < 2; ++k) {
            ghm_elem(xA[k].x, tA[k].x, rowbase);
            ghm_elem(xA[k].y, tA[k].y, rowbase);
            ghm_elem(xA[k].z, tA[k].z, rowbase);
            ghm_elem(xA[k].w, tA[k].w, rowbase);
        }
    }

    // Ragged float4 tail.
    for (int i = idx + full * per_it; i < n4; i += stride4) {
        const float4 xv = __ldcs(&x4[i]);
        const int4   tv = __ldcs(&t4[i]);
        ghm_elem(xv.x, tv.x, rowbase);
        ghm_elem(xv.y, tv.y, rowbase);
        ghm_elem(xv.z, tv.z, rowbase);
        ghm_elem(xv.w, tv.w, rowbase);
    }

    // Scalar tail (n % 4), block 0 only.
    if (blockIdx.x == 0 && tid < (n & 3)) {
        const int i = (n & ~3) + tid;
        ghm_elem(x[i], tg[i], rowbase);
    }

    // ── Split S = 4096*cnt + sum(l); reduce: warp butterfly -> block -> global ──
    float sums[BINS], cnts[BINS];
    #pragma unroll
    for (int b = 0; b < BINS; ++b) {
        const float S = rows[b][tid];      // own cell only; no sync needed
        const float c = rintf(S * KINV);   // count (sum(l) per thread-bin < 2048)
        cnts[b] = c;
        sums[b] = S - c * KBIG;            // sum of log2(p), small residual error ok
    }
    #pragma unroll
    for (int b = 0; b < BINS; ++b) {
        #pragma unroll
        for (int o = 16; o; o >>= 1) {
            sums[b] += __shfl_xor_sync(0xffffffffu, sums[b], o);
            cnts[b] += __shfl_xor_sync(0xffffffffu, cnts[b], o);
        }
    }
    if (tid < 2 * BINS) sh_fin[tid] = 0.0f;
    __syncthreads();
    if ((tid & 31) == 0) {
        #pragma unroll
        for (int b = 0; b < BINS; ++b) {
            atomicAdd(&sh_fin[b], sums[b]);
            atomicAdd(&sh_fin[BINS + b], cnts[b]);
        }
    }
    __syncthreads();
    if (tid < BINS) {
        atomicAdd(&g_sum[tid], sh_fin[tid]);
        atomicAdd(&g_cnt[tid], sh_fin[BINS + tid]);
    }

    // Last-block ticket: finalize + reset scratch for next graph replay.
    __threadfence();
    if (tid == 0) {
        const unsigned t = atomicAdd(&g_ticket, 1u);
        s_last = (t == (unsigned)(GRID - 1));
    }
    __syncthreads();
    if (s_last && tid < 32) {
        float c = 0.0f, ssum = 0.0f;
        if (tid < BINS) {
            c    = atomicAdd(&g_cnt[tid], 0.0f);   // coherent L2 read
            ssum = atomicAdd(&g_sum[tid], 0.0f);
        }
        const unsigned ne = __ballot_sync(0xffffffffu, (tid < BINS) && (c > 0.5f));
        const float nonempty = (float)__popc(ne);
        float term = 0.0f;
        if (tid < BINS)
            term = (LN2 * ssum) / fmaxf(c * nonempty, 1e-6f);  // deferred ln2 scale
        #pragma unroll
        for (int o = 16; o; o >>= 1)
            term += __shfl_xor_sync(0xffffffffu, term, o);
        for (int i = tid; i < out_size; i += 32) out[i] = term;
        if (tid < BINS) { g_sum[tid] = 0.0f; g_cnt[tid] = 0.0f; }
        if (tid == 0) g_ticket = 0u;
    }
}

extern "C" void kernel_launch(void* const* d_in, const int* in_sizes, int n_in,
                              void* d_out, int out_size) {
    const float* x = (const float*)d_in[0];
    const int*   t = (const int*)d_in[1];
    const int n = in_sizes[0];
    ghm_fused<<<GRID, BLOCK>>>(x, t, n, (float*)d_out, out_size);
}

// round 16
// speedup vs baseline: 1.2020x; 1.0011x over previous
#include <cuda_runtime.h>

#define BINS  10
#define BLOCK 256
#define OCC   4
#define GRID  (148 * OCC)

// Global scratch (zero at module load; reset by last block each run -> graph-replayable).
__device__ float    g_sum[BINS];
__device__ float    g_cnt[BINS];
__device__ unsigned g_ticket;

#define LOG2E 1.4426950408889634f
#define LN2   0.69314718055994531f
#define KBIG  4096.0f            // count embedded as multiples of 4096 in the same float
#define KINV  (1.0f / 4096.0f)

__device__ __forceinline__ float ex2_approx(float x) {
    float r; asm("ex2.approx.f32 %0, %1;" : "=f"(r) : "f"(x)); return r;   // MUFU.EX2
}
__device__ __forceinline__ float lg2_approx(float x) {
    float r; asm("lg2.approx.f32 %0, %1;" : "=f"(r) : "f"(x)); return r;   // MUFU.LG2
}
__device__ __forceinline__ float rcp_approx(float x) {
    float r; asm("rcp.approx.f32 %0, %1;" : "=f"(r) : "f"(x)); return r;   // MUFU.RCP
}

__shared__ float rows[BINS][BLOCK];    // [bin][tid]; S = 4096*cnt + sum(log2 p)
                                       // bank = tid mod 32 -> conflict-free for any bin

// Direct 2D shared indexing: guaranteed LDS/STS (no generic-pointer fallback).
__device__ __forceinline__ void ghm_elem(float xx, int tt, int tid) {
    // z = x if t==0 else -x: sign-bit flip via single XOR.
    const int   zi = __float_as_int(xx) ^ (tt << 31);
    const float z  = __int_as_float(zi);
    const float a  = ex2_approx(z * LOG2E);       // e^z      (FMUL + MUFU.EX2)
    const float p  = 1.0f + a;                    // 1 + e^z  (inf-safe)
    const float l  = lg2_approx(p);               // ce = ln2 * l (scaled at finalize)
    const float r  = rcp_approx(p);               // sigmoid(z) = 1 - r
    const float g9 = 9.9999f - 9.9999f * r;       // FFMA: g*(BINS-1e-4) in [0, 9.9999)
    const int  bin = (int)g9;                     // F2I trunc; p=inf -> r=0 -> bin 9
    rows[bin][tid] += (l + KBIG);                 // LDS.32 + 2 FADD + STS.32
}

__device__ __forceinline__ void consume8(const float4& x0, const float4& x1,
                                         const int4& t0, const int4& t1, int tid) {
    ghm_elem(x0.x, t0.x, tid); ghm_elem(x0.y, t0.y, tid);
    ghm_elem(x0.z, t0.z, tid); ghm_elem(x0.w, t0.w, tid);
    ghm_elem(x1.x, t1.x, tid); ghm_elem(x1.y, t1.y, tid);
    ghm_elem(x1.z, t1.z, tid); ghm_elem(x1.w, t1.w, tid);
}

__global__ void __launch_bounds__(BLOCK, OCC)
ghm_fused(const float* __restrict__ x, const int* __restrict__ tg, int n,
          float* __restrict__ out, int out_size) {
    __shared__ float sh_fin[2 * BINS];
    __shared__ bool  s_last;

    const int tid = threadIdx.x;
    #pragma unroll
    for (int b = 0; b < BINS; ++b) rows[b][tid] = 0.0f;

    const int n4 = n >> 2;
    constexpr int stride4 = GRID * BLOCK;     // compile-time: enables [R+imm] addressing
    constexpr int per_it  = 2 * stride4;      // 8 elems/thread per phase
    const int idx  = blockIdx.x * BLOCK + tid;
    const int full = n4 / per_it;             // fully-valid phases (uniform)
    const float4* __restrict__ x4 = (const float4*)x;
    const int4*   __restrict__ t4 = (const int4*)tg;

#define LOADP(X0, X1, T0, T1, IT)                                   \
    do {                                                            \
        const int _b = idx + (IT) * per_it;                         \
        X0 = __ldcs(&x4[_b]); X1 = __ldcs(&x4[_b + stride4]);       \
        T0 = __ldcs(&t4[_b]); T1 = __ldcs(&t4[_b + stride4]);       \
    } while (0)

    // ── Two-phase software pipeline (A/B roles alternate, no register copies) ──
    float4 xA0, xA1, xB0, xB1; int4 tA0, tA1, tB0, tB1;
    int it = 0;
    if (full > 0) {
        LOADP(xA0, xA1, tA0, tA1, 0);
        for (; it + 2 < full; it += 2) {
            LOADP(xB0, xB1, tB0, tB1, it + 1);
            consume8(xA0, xA1, tA0, tA1, tid);
            LOADP(xA0, xA1, tA0, tA1, it + 2);
            consume8(xB0, xB1, tB0, tB1, tid);
        }
        if (it + 1 < full) {                  // 2 phases remain
            LOADP(xB0, xB1, tB0, tB1, it + 1);
            consume8(xA0, xA1, tA0, tA1, tid);
            consume8(xB0, xB1, tB0, tB1, tid);
        } else {                              // 1 phase remains
            consume8(xA0, xA1, tA0, tA1, tid);
        }
    }
#undef LOADP

    // Ragged float4 tail.
    for (int i = idx + full * per_it; i < n4; i += stride4) {
        const float4 xv = __ldcs(&x4[i]);
        const int4   tv = __ldcs(&t4[i]);
        ghm_elem(xv.x, tv.x, tid);
        ghm_elem(xv.y, tv.y, tid);
        ghm_elem(xv.z, tv.z, tid);
        ghm_elem(xv.w, tv.w, tid);
    }

    // Scalar tail (n % 4), block 0 only.
    if (blockIdx.x == 0 && tid < (n & 3)) {
        const int i = (n & ~3) + tid;
        ghm_elem(x[i], tg[i], tid);
    }

    // ── Split S = 4096*cnt + sum(l); reduce: warp butterfly -> block -> global ──
    float sums[BINS], cnts[BINS];
    #pragma unroll
    for (int b = 0; b < BINS; ++b) {
        const float S = rows[b][tid];      // own cell only; no sync needed
        const float c = rintf(S * KINV);   // count (sum(l) per thread-bin < 2048)
        cnts[b] = c;
        sums[b] = S - c * KBIG;            // sum of log2(p)
    }
    #pragma unroll
    for (int b = 0; b < BINS; ++b) {
        #pragma unroll
        for (int o = 16; o; o >>= 1) {
            sums[b] += __shfl_xor_sync(0xffffffffu, sums[b], o);
            cnts[b] += __shfl_xor_sync(0xffffffffu, cnts[b], o);
        }
    }
    if (tid < 2 * BINS) sh_fin[tid] = 0.0f;
    __syncthreads();
    if ((tid & 31) == 0) {
        #pragma unroll
        for (int b = 0; b < BINS; ++b) {
            atomicAdd(&sh_fin[b], sums[b]);
            atomicAdd(&sh_fin[BINS + b], cnts[b]);
        }
    }
    __syncthreads();
    if (tid < BINS) {
        atomicAdd(&g_sum[tid], sh_fin[tid]);
        atomicAdd(&g_cnt[tid], sh_fin[BINS + tid]);
    }

    // Last-block ticket: finalize + reset scratch for next graph replay.
    __threadfence();
    if (tid == 0) {
        const unsigned t = atomicAdd(&g_ticket, 1u);
        s_last = (t == (unsigned)(GRID - 1));
    }
    __syncthreads();
    if (s_last && tid < 32) {
        float c = 0.0f, ssum = 0.0f;
        if (tid < BINS) {
            c    = atomicAdd(&g_cnt[tid], 0.0f);   // coherent L2 read
            ssum = atomicAdd(&g_sum[tid], 0.0f);
        }
        const unsigned ne = __ballot_sync(0xffffffffu, (tid < BINS) && (c > 0.5f));
        const float nonempty = (float)__popc(ne);
        float term = 0.0f;
        if (tid < BINS)
            term = (LN2 * ssum) / fmaxf(c * nonempty, 1e-6f);  // deferred ln2 scale
        #pragma unroll
        for (int o = 16; o; o >>= 1)
            term += __shfl_xor_sync(0xffffffffu, term, o);
        for (int i = tid; i < out_size; i += 32) out[i] = term;
        if (tid < BINS) { g_sum[tid] = 0.0f; g_cnt[tid] = 0.0f; }
        if (tid == 0) g_ticket = 0u;
    }
}

extern "C" void kernel_launch(void* const* d_in, const int* in_sizes, int n_in,
                              void* d_out, int out_size) {
    const float* x = (const float*)d_in[0];
    const int*   t = (const int*)d_in[1];
    const int n = in_sizes[0];
    ghm_fused<<<GRID, BLOCK>>>(x, t, n, (float*)d_out, out_size);
}